// round 9
// baseline (speedup 1.0000x reference)
#include <cuda_runtime.h>

#define N_NODES 100000
#define HEADS 4
#define HIDDEN 32

// Device-global scratch (no allocation allowed).
// g_acc[n][h] = {Tx, Ty, Tz, S}: T = sum_e attn_h * rel_e into node n, S = sum_e attn_h.
__device__ __align__(16) float4 g_acc[N_NODES][HEADS];
__device__ __align__(16) float4 g_pos4[N_NODES];
// Score constants, 12 floats per head (10 used, 2 pad):
// {Pxx, Pyy, Pzz, Pxy, Pxz, Pyz, Lx, Ly, Lz, C, pad, pad}
__device__ __align__(16) float g_K[HEADS * 12];
__device__ float g_A[HEADS][3][HIDDEN];  // Wv_h^T @ Wout_h
__device__ float g_U[HEADS][HIDDEN];     // bv_h @ Wout_h
__device__ int   g_is64;                 // edge_index dtype flag

// ---------------------------------------------------------------------------
// init: zero accumulators, pack positions to float4, detect index dtype,
// and precompute all folded coefficients. One launch.
// ---------------------------------------------------------------------------
__global__ void init_kernel(const float* __restrict__ pos, const void* __restrict__ ei_raw,
                            const float* __restrict__ Wq, const float* __restrict__ bq,
                            const float* __restrict__ Wk, const float* __restrict__ bk,
                            const float* __restrict__ Wv, const float* __restrict__ bv,
                            const float* __restrict__ Wout, int E) {
    int idx = blockIdx.x * blockDim.x + threadIdx.x;
    int stride = gridDim.x * blockDim.x;

    float4* acc = &g_acc[0][0];
    for (int i = idx; i < N_NODES * HEADS; i += stride)
        acc[i] = make_float4(0.f, 0.f, 0.f, 0.f);
    for (int i = idx; i < N_NODES; i += stride)
        g_pos4[i] = make_float4(pos[3 * i], pos[3 * i + 1], pos[3 * i + 2], 0.f);

    if (blockIdx.x == 1) {
        // dtype detection: interpret first 128 entries as int64; all being valid
        // node ids identifies a true int64 buffer (false-positive prob ~1e-640
        // for an int32 buffer whose high words are random indices).
        __shared__ int ok;
        if (threadIdx.x == 0) ok = 1;
        __syncthreads();
        int n = 2 * E < 128 ? 2 * E : 128;
        if (threadIdx.x < n) {
            long long v = ((const long long*)ei_raw)[threadIdx.x];
            if (v < 0 || v >= N_NODES) atomicAnd(&ok, 0);
        }
        __syncthreads();
        if (threadIdx.x == 0) g_is64 = ok;
    }

    if (blockIdx.x == 0) {
        const float scale = rsqrtf((float)HIDDEN);
        for (int u = threadIdx.x; u < 552; u += blockDim.x) {
            if (u < 24) {
                // symmetrized quadratic coefficients
                int h = u / 6, s = u % 6;
                const int pi[6] = {0, 1, 2, 0, 0, 1};
                const int pj[6] = {0, 1, 2, 1, 2, 2};
                int i = pi[s], j = pj[s];
                float a = 0.f;
                for (int d = 0; d < HIDDEN; d++) {
                    float t = Wq[i * 128 + h * 32 + d] * Wk[j * 128 + h * 32 + d];
                    if (i != j) t += Wq[j * 128 + h * 32 + d] * Wk[i * 128 + h * 32 + d];
                    a += t;
                }
                g_K[h * 12 + s] = a * scale;
            } else if (u < 36) {
                int v = u - 24; int h = v / 3, i = v % 3;
                float a = 0.f;
                for (int d = 0; d < HIDDEN; d++)
                    a += Wq[i * 128 + h * 32 + d] * bk[h * 32 + d]
                       + Wk[i * 128 + h * 32 + d] * bq[h * 32 + d];
                g_K[h * 12 + 6 + i] = a * scale;
            } else if (u < 40) {
                int h = u - 36;
                float a = 0.f;
                for (int d = 0; d < HIDDEN; d++) a += bq[h * 32 + d] * bk[h * 32 + d];
                g_K[h * 12 + 9] = a * scale;
            } else if (u < 424) {
                int v = u - 40; int h = v / 96; int r = v % 96; int i = r / 32, m = r % 32;
                float a = 0.f;
                for (int d = 0; d < HIDDEN; d++)
                    a += Wv[i * 128 + h * 32 + d] * Wout[(h * 32 + d) * 32 + m];
                g_A[h][i][m] = a;
            } else {
                int v = u - 424; int h = v / 32, m = v % 32;
                float a = 0.f;
                for (int d = 0; d < HIDDEN; d++)
                    a += bv[h * 32 + d] * Wout[(h * 32 + d) * 32 + m];
                g_U[h][m] = a;
            }
        }
    }
}

// ---------------------------------------------------------------------------
// edge kernel: 2 edges/thread, shared-staged constants, float4 gathers,
// 4x red.global.add.v4.f32 per edge into [node][head] layout.
// ---------------------------------------------------------------------------
__device__ __forceinline__ void process_edge(const float* __restrict__ sk,
                                             float4 pr, float4 pc, int c) {
    float rx = pr.x - pc.x, ry = pr.y - pc.y, rz = pr.z - pc.z;
    float xx = rx * rx, yy = ry * ry, zz = rz * rz;
    float xy = rx * ry, xz = rx * rz, yz = ry * rz;

    float sc[HEADS];
#pragma unroll
    for (int h = 0; h < HEADS; h++) {
        const float* k = sk + h * 12;
        float a = fmaf(k[0], xx, fmaf(k[1], yy, fmaf(k[2], zz, k[9])));
        float b = fmaf(k[3], xy, fmaf(k[4], xz, k[5] * yz));
        float d = fmaf(k[6], rx, fmaf(k[7], ry, k[8] * rz));
        sc[h] = a + b + d;
    }
    float mx = fmaxf(fmaxf(sc[0], sc[1]), fmaxf(sc[2], sc[3]));
    float ex[HEADS]; float sum = 0.f;
#pragma unroll
    for (int h = 0; h < HEADS; h++) { ex[h] = __expf(sc[h] - mx); sum += ex[h]; }
    float inv = 1.f / sum;

#pragma unroll
    for (int h = 0; h < HEADS; h++) {
        float a = ex[h] * inv;
        float4* p = &g_acc[c][h];
        asm volatile("red.global.add.v4.f32 [%0], {%1, %2, %3, %4};"
                     :: "l"(p), "f"(a * rx), "f"(a * ry), "f"(a * rz), "f"(a)
                     : "memory");
    }
}

__global__ void __launch_bounds__(256) edge_kernel(const void* __restrict__ ei_raw, int E) {
    __shared__ float sk[HEADS * 12];
    if (threadIdx.x < HEADS * 12) sk[threadIdx.x] = g_K[threadIdx.x];
    __syncthreads();

    int t = blockIdx.x * blockDim.x + threadIdx.x;
    int e0 = 2 * t, e1 = 2 * t + 1;
    bool v0 = e0 < E, v1 = e1 < E;
    if (!v0) return;

    int r0 = 0, c0 = 0, r1 = 0, c1 = 0;
    if (g_is64) {
        const long long* ei = (const long long*)ei_raw;
        r0 = (int)ei[e0]; c0 = (int)ei[E + e0];
        if (v1) { r1 = (int)ei[e1]; c1 = (int)ei[E + e1]; }
    } else {
        const int* ei = (const int*)ei_raw;
        r0 = ei[e0]; c0 = ei[E + e0];
        if (v1) { r1 = ei[e1]; c1 = ei[E + e1]; }
    }

    // issue all gathers up front for MLP
    float4 pr0 = g_pos4[r0];
    float4 pc0 = g_pos4[c0];
    float4 pr1, pc1;
    if (v1) { pr1 = g_pos4[r1]; pc1 = g_pos4[c1]; }

    process_edge(sk, pr0, pc0, c0);
    if (v1) process_edge(sk, pr1, pc1, c1);
}

// ---------------------------------------------------------------------------
// node kernel: 1 warp/node; 16-float contraction, warp LayerNorm, SiLU.
// ---------------------------------------------------------------------------
__global__ void node_kernel(const float* __restrict__ bout, const float* __restrict__ gamma,
                            const float* __restrict__ beta, float* __restrict__ out) {
    int gtid = blockIdx.x * blockDim.x + threadIdx.x;
    int n = gtid >> 5;
    int lane = gtid & 31;
    if (n >= N_NODES) return;

    float4 t0 = g_acc[n][0];
    float4 t1 = g_acc[n][1];
    float4 t2 = g_acc[n][2];
    float4 t3 = g_acc[n][3];
    // count = sum_h S_h (softmax over heads sums to 1 per edge)
    float cnt = t0.w + t1.w + t2.w + t3.w;
    float invc = 1.f / fmaxf(cnt, 1.f);

    float acc =
          t0.x * g_A[0][0][lane] + t0.y * g_A[0][1][lane] + t0.z * g_A[0][2][lane] + t0.w * g_U[0][lane]
        + t1.x * g_A[1][0][lane] + t1.y * g_A[1][1][lane] + t1.z * g_A[1][2][lane] + t1.w * g_U[1][lane]
        + t2.x * g_A[2][0][lane] + t2.y * g_A[2][1][lane] + t2.z * g_A[2][2][lane] + t2.w * g_U[2][lane]
        + t3.x * g_A[3][0][lane] + t3.y * g_A[3][1][lane] + t3.z * g_A[3][2][lane] + t3.w * g_U[3][lane];

    float val = acc * invc + bout[lane];

    float s = val, ss = val * val;
#pragma unroll
    for (int o = 16; o > 0; o >>= 1) {
        s  += __shfl_xor_sync(0xffffffffu, s, o);
        ss += __shfl_xor_sync(0xffffffffu, ss, o);
    }
    float mu  = s * (1.f / 32.f);
    float var = ss * (1.f / 32.f) - mu * mu;
    float y = (val - mu) * rsqrtf(var + 1e-5f) * gamma[lane] + beta[lane];
    out[n * 32 + lane] = y * (1.f / (1.f + __expf(-y)));
}

extern "C" void kernel_launch(void* const* d_in, const int* in_sizes, int n_in,
                              void* d_out, int out_size) {
    const float* pos   = (const float*)d_in[0];
    const void*  ei    = d_in[1];
    const float* Wq    = (const float*)d_in[2];
    const float* bq    = (const float*)d_in[3];
    const float* Wk    = (const float*)d_in[4];
    const float* bk    = (const float*)d_in[5];
    const float* Wv    = (const float*)d_in[6];
    const float* bv    = (const float*)d_in[7];
    const float* Wout  = (const float*)d_in[8];
    const float* bout  = (const float*)d_in[9];
    const float* gamma = (const float*)d_in[10];
    const float* beta  = (const float*)d_in[11];
    float* out = (float*)d_out;

    int E = in_sizes[1] / 2;

    init_kernel<<<592, 256>>>(pos, ei, Wq, bq, Wk, bk, Wv, bv, Wout, E);
    edge_kernel<<<(E + 511) / 512, 256>>>(ei, E);
    node_kernel<<<(N_NODES * 32 + 255) / 256, 256>>>(bout, gamma, beta, out);
}

// round 11
// speedup vs baseline: 1.3316x; 1.3316x over previous
#include <cuda_runtime.h>

#define N_NODES 100000
#define HEADS 4
#define HIDDEN 32

// Device-global scratch (no allocation allowed).
// g_acc[h][n] = {Tx, Ty, Tz, S}: spread across heads-major so one edge's 4 reds
// hit 4 different L2 slices (per-slice atomic ALU serializes).
__device__ __align__(16) float4 g_acc[HEADS][N_NODES];
__device__ __align__(16) float4 g_pos4[N_NODES];
// Score constants, 12 floats per head (10 used, 2 pad):
// {Pxx, Pyy, Pzz, Pxy, Pxz, Pyz, Lx, Ly, Lz, C, pad, pad}
__device__ __align__(16) float g_K[HEADS * 12];
__device__ float g_A[HEADS][3][HIDDEN];  // Wv_h^T @ Wout_h
__device__ float g_U[HEADS][HIDDEN];     // bv_h @ Wout_h
__device__ int   g_is64;                 // edge_index dtype flag

// ---------------------------------------------------------------------------
// init: one launch. Block 0: precompute only (starts immediately).
// Block 1: dtype detect + share of zero/pack. Blocks 1..: zero acc, pack pos.
// ---------------------------------------------------------------------------
__global__ void init_kernel(const float* __restrict__ pos, const void* __restrict__ ei_raw,
                            const float* __restrict__ Wq, const float* __restrict__ bq,
                            const float* __restrict__ Wk, const float* __restrict__ bk,
                            const float* __restrict__ Wv, const float* __restrict__ bv,
                            const float* __restrict__ Wout, int E) {
    if (blockIdx.x == 0) {
        const float scale = rsqrtf((float)HIDDEN);
        for (int u = threadIdx.x; u < 552; u += blockDim.x) {
            if (u < 24) {
                // symmetrized quadratic coefficients
                int h = u / 6, s = u % 6;
                const int pi[6] = {0, 1, 2, 0, 0, 1};
                const int pj[6] = {0, 1, 2, 1, 2, 2};
                int i = pi[s], j = pj[s];
                float a = 0.f;
#pragma unroll 4
                for (int d = 0; d < HIDDEN; d++) {
                    float t = Wq[i * 128 + h * 32 + d] * Wk[j * 128 + h * 32 + d];
                    if (i != j) t += Wq[j * 128 + h * 32 + d] * Wk[i * 128 + h * 32 + d];
                    a += t;
                }
                g_K[h * 12 + s] = a * scale;
            } else if (u < 36) {
                int v = u - 24; int h = v / 3, i = v % 3;
                float a = 0.f;
#pragma unroll 4
                for (int d = 0; d < HIDDEN; d++)
                    a += Wq[i * 128 + h * 32 + d] * bk[h * 32 + d]
                       + Wk[i * 128 + h * 32 + d] * bq[h * 32 + d];
                g_K[h * 12 + 6 + i] = a * scale;
            } else if (u < 40) {
                int h = u - 36;
                float a = 0.f;
#pragma unroll 4
                for (int d = 0; d < HIDDEN; d++) a += bq[h * 32 + d] * bk[h * 32 + d];
                g_K[h * 12 + 9] = a * scale;
            } else if (u < 424) {
                int v = u - 40; int h = v / 96; int r = v % 96; int i = r / 32, m = r % 32;
                float a = 0.f;
#pragma unroll 4
                for (int d = 0; d < HIDDEN; d++)
                    a += Wv[i * 128 + h * 32 + d] * Wout[(h * 32 + d) * 32 + m];
                g_A[h][i][m] = a;
            } else {
                int v = u - 424; int h = v / 32, m = v % 32;
                float a = 0.f;
#pragma unroll 4
                for (int d = 0; d < HIDDEN; d++)
                    a += bv[h * 32 + d] * Wout[(h * 32 + d) * 32 + m];
                g_U[h][m] = a;
            }
        }
        return;
    }

    if (blockIdx.x == 1) {
        // dtype detection: interpret first 128 entries as int64; all being valid
        // node ids identifies a true int64 buffer (false-positive prob ~1e-640
        // for an int32 buffer whose high words are random indices).
        __shared__ int ok;
        if (threadIdx.x == 0) ok = 1;
        __syncthreads();
        int n = 2 * E < 128 ? 2 * E : 128;
        if (threadIdx.x < n) {
            long long v = ((const long long*)ei_raw)[threadIdx.x];
            if (v < 0 || v >= N_NODES) atomicAnd(&ok, 0);
        }
        __syncthreads();
        if (threadIdx.x == 0) g_is64 = ok;
    }

    int idx = (blockIdx.x - 1) * blockDim.x + threadIdx.x;
    int stride = (gridDim.x - 1) * blockDim.x;
    float4* acc = &g_acc[0][0];
    for (int i = idx; i < N_NODES * HEADS; i += stride)
        acc[i] = make_float4(0.f, 0.f, 0.f, 0.f);
    for (int i = idx; i < N_NODES; i += stride)
        g_pos4[i] = make_float4(pos[3 * i], pos[3 * i + 1], pos[3 * i + 2], 0.f);
}

// ---------------------------------------------------------------------------
// edge kernel: 1 edge/thread, shared-staged score constants, float4 gathers,
// 4x red.global.add.v4.f32 spread across 4 head planes.
// ---------------------------------------------------------------------------
__global__ void __launch_bounds__(256) edge_kernel(const void* __restrict__ ei_raw, int E) {
    __shared__ float sk[HEADS * 12];
    if (threadIdx.x < HEADS * 12) sk[threadIdx.x] = g_K[threadIdx.x];
    __syncthreads();

    int e = blockIdx.x * blockDim.x + threadIdx.x;
    if (e >= E) return;

    int r, c;
    if (g_is64) {
        const long long* ei = (const long long*)ei_raw;
        r = (int)ei[e]; c = (int)ei[E + e];
    } else {
        const int* ei = (const int*)ei_raw;
        r = ei[e]; c = ei[E + e];
    }

    float4 pr = g_pos4[r];
    float4 pc = g_pos4[c];
    float rx = pr.x - pc.x, ry = pr.y - pc.y, rz = pr.z - pc.z;
    float xx = rx * rx, yy = ry * ry, zz = rz * rz;
    float xy = rx * ry, xz = rx * rz, yz = ry * rz;

    float sc[HEADS];
#pragma unroll
    for (int h = 0; h < HEADS; h++) {
        const float* k = sk + h * 12;
        float a = fmaf(k[0], xx, fmaf(k[1], yy, fmaf(k[2], zz, k[9])));
        float b = fmaf(k[3], xy, fmaf(k[4], xz, k[5] * yz));
        float d = fmaf(k[6], rx, fmaf(k[7], ry, k[8] * rz));
        sc[h] = a + b + d;
    }
    float mx = fmaxf(fmaxf(sc[0], sc[1]), fmaxf(sc[2], sc[3]));
    float ex[HEADS]; float sum = 0.f;
#pragma unroll
    for (int h = 0; h < HEADS; h++) { ex[h] = __expf(sc[h] - mx); sum += ex[h]; }
    float inv = 1.f / sum;

#pragma unroll
    for (int h = 0; h < HEADS; h++) {
        float a = ex[h] * inv;
        float4* p = &g_acc[h][c];
        asm volatile("red.global.add.v4.f32 [%0], {%1, %2, %3, %4};"
                     :: "l"(p), "f"(a * rx), "f"(a * ry), "f"(a * rz), "f"(a)
                     : "memory");
    }
}

// ---------------------------------------------------------------------------
// node kernel: 1 warp/node; 16-float contraction, warp LayerNorm, SiLU.
// ---------------------------------------------------------------------------
__global__ void node_kernel(const float* __restrict__ bout, const float* __restrict__ gamma,
                            const float* __restrict__ beta, float* __restrict__ out) {
    int gtid = blockIdx.x * blockDim.x + threadIdx.x;
    int n = gtid >> 5;
    int lane = gtid & 31;
    if (n >= N_NODES) return;

    float4 t0 = g_acc[0][n];
    float4 t1 = g_acc[1][n];
    float4 t2 = g_acc[2][n];
    float4 t3 = g_acc[3][n];
    // count = sum_h S_h (softmax over heads sums to 1 per edge)
    float cnt = t0.w + t1.w + t2.w + t3.w;
    float invc = 1.f / fmaxf(cnt, 1.f);

    float acc =
          t0.x * g_A[0][0][lane] + t0.y * g_A[0][1][lane] + t0.z * g_A[0][2][lane] + t0.w * g_U[0][lane]
        + t1.x * g_A[1][0][lane] + t1.y * g_A[1][1][lane] + t1.z * g_A[1][2][lane] + t1.w * g_U[1][lane]
        + t2.x * g_A[2][0][lane] + t2.y * g_A[2][1][lane] + t2.z * g_A[2][2][lane] + t2.w * g_U[2][lane]
        + t3.x * g_A[3][0][lane] + t3.y * g_A[3][1][lane] + t3.z * g_A[3][2][lane] + t3.w * g_U[3][lane];

    float val = acc * invc + bout[lane];

    float s = val, ss = val * val;
#pragma unroll
    for (int o = 16; o > 0; o >>= 1) {
        s  += __shfl_xor_sync(0xffffffffu, s, o);
        ss += __shfl_xor_sync(0xffffffffu, ss, o);
    }
    float mu  = s * (1.f / 32.f);
    float var = ss * (1.f / 32.f) - mu * mu;
    float y = (val - mu) * rsqrtf(var + 1e-5f) * gamma[lane] + beta[lane];
    out[n * 32 + lane] = y * (1.f / (1.f + __expf(-y)));
}

extern "C" void kernel_launch(void* const* d_in, const int* in_sizes, int n_in,
                              void* d_out, int out_size) {
    const float* pos   = (const float*)d_in[0];
    const void*  ei    = d_in[1];
    const float* Wq    = (const float*)d_in[2];
    const float* bq    = (const float*)d_in[3];
    const float* Wk    = (const float*)d_in[4];
    const float* bk    = (const float*)d_in[5];
    const float* Wv    = (const float*)d_in[6];
    const float* bv    = (const float*)d_in[7];
    const float* Wout  = (const float*)d_in[8];
    const float* bout  = (const float*)d_in[9];
    const float* gamma = (const float*)d_in[10];
    const float* beta  = (const float*)d_in[11];
    float* out = (float*)d_out;

    int E = in_sizes[1] / 2;

    init_kernel<<<593, 256>>>(pos, ei, Wq, bq, Wk, bk, Wv, bv, Wout, E);
    edge_kernel<<<(E + 255) / 256, 256>>>(ei, E);
    node_kernel<<<(N_NODES * 32 + 255) / 256, 256>>>(bout, gamma, beta, out);
}

// round 12
// speedup vs baseline: 1.5350x; 1.1527x over previous
#include <cuda_runtime.h>

#define N_NODES 100000
#define HEADS 4
#define HIDDEN 32

// Device-global scratch (no allocation allowed).
// g_acc[h][n] = {Tx, Ty, Tz, S}: heads-major so one edge's 4 reds hit 4
// different L2 slices (per-slice atomic ALU serializes).
__device__ __align__(16) float4 g_acc[HEADS][N_NODES];
__device__ float g_M[HEADS][3][3];       // quadratic form (pre-scaled by 1/sqrt(32))
__device__ float g_L[HEADS][3];          // linear term from biases
__device__ float g_C[HEADS];             // constant term from biases
__device__ float g_A[HEADS][3][HIDDEN];  // Wv_h^T @ Wout_h
__device__ float g_U[HEADS][HIDDEN];     // bv_h @ Wout_h
__device__ int   g_is64;                 // edge_index dtype flag

// ---------------------------------------------------------------------------
// init (single launch):
//   block 0              : precompute folded coefficients only
//   block 1              : parallel dtype detect, then joins zeroing
//   blocks 1..NZB        : zero g_acc, exactly one float4 per thread
// ---------------------------------------------------------------------------
#define NZB ((N_NODES * HEADS + 255) / 256)   // 1563 zero-blocks

__global__ void init_kernel(const void* __restrict__ ei_raw,
                            const float* __restrict__ Wq, const float* __restrict__ bq,
                            const float* __restrict__ Wk, const float* __restrict__ bk,
                            const float* __restrict__ Wv, const float* __restrict__ bv,
                            const float* __restrict__ Wout, int E) {
    if (blockIdx.x == 0) {
        const float scale = rsqrtf((float)HIDDEN);
        for (int t = threadIdx.x; t < 564; t += blockDim.x) {
            if (t < 36) {
                int h = t / 9, i = (t % 9) / 3, j = t % 3;
                float s = 0.f;
#pragma unroll 8
                for (int d = 0; d < HIDDEN; d++)
                    s += Wq[i * 128 + h * 32 + d] * Wk[j * 128 + h * 32 + d];
                g_M[h][i][j] = s * scale;
            } else if (t < 48) {
                int u = t - 36; int h = u / 3, i = u % 3;
                float s = 0.f;
#pragma unroll 8
                for (int d = 0; d < HIDDEN; d++)
                    s += Wq[i * 128 + h * 32 + d] * bk[h * 32 + d]
                       + Wk[i * 128 + h * 32 + d] * bq[h * 32 + d];
                g_L[h][i] = s * scale;
            } else if (t < 52) {
                int h = t - 48;
                float s = 0.f;
#pragma unroll 8
                for (int d = 0; d < HIDDEN; d++) s += bq[h * 32 + d] * bk[h * 32 + d];
                g_C[h] = s * scale;
            } else if (t < 436) {
                int u = t - 52; int h = u / 96; int r = u % 96; int i = r / 32, m = r % 32;
                float s = 0.f;
#pragma unroll 8
                for (int d = 0; d < HIDDEN; d++)
                    s += Wv[i * 128 + h * 32 + d] * Wout[(h * 32 + d) * 32 + m];
                g_A[h][i][m] = s;
            } else {
                int u = t - 436; int h = u / 32, m = u % 32;
                float s = 0.f;
#pragma unroll 8
                for (int d = 0; d < HIDDEN; d++)
                    s += bv[h * 32 + d] * Wout[(h * 32 + d) * 32 + m];
                g_U[h][m] = s;
            }
        }
        return;
    }

    if (blockIdx.x == 1) {
        // dtype detection: interpret first 128 entries as int64; all being valid
        // node ids identifies a true int64 buffer (false-positive prob ~1e-640
        // for an int32 buffer whose high words are random indices).
        __shared__ int ok;
        if (threadIdx.x == 0) ok = 1;
        __syncthreads();
        int n = 2 * E < 128 ? 2 * E : 128;
        if (threadIdx.x < n) {
            long long v = ((const long long*)ei_raw)[threadIdx.x];
            if (v < 0 || v >= N_NODES) atomicAnd(&ok, 0);
        }
        __syncthreads();
        if (threadIdx.x == 0) g_is64 = ok;
    }

    int i = (blockIdx.x - 1) * blockDim.x + threadIdx.x;
    if (i < N_NODES * HEADS)
        (&g_acc[0][0])[i] = make_float4(0.f, 0.f, 0.f, 0.f);
}

// ---------------------------------------------------------------------------
// edge kernel: exact R8 body (measured 20.9us). 1 edge/thread, 6 scalar
// gathers (MLP=6), uniform constant LDGs, 4x red.global.add.v4.f32.
// ---------------------------------------------------------------------------
__global__ void edge_kernel(const float* __restrict__ pos,
                            const void* __restrict__ ei_raw, int E) {
    int e = blockIdx.x * blockDim.x + threadIdx.x;
    if (e >= E) return;

    int r, c;
    if (g_is64) {
        const long long* ei = (const long long*)ei_raw;
        r = (int)ei[e];
        c = (int)ei[E + e];
    } else {
        const int* ei = (const int*)ei_raw;
        r = ei[e];
        c = ei[E + e];
    }

    float rx = __ldg(&pos[3 * r + 0]) - __ldg(&pos[3 * c + 0]);
    float ry = __ldg(&pos[3 * r + 1]) - __ldg(&pos[3 * c + 1]);
    float rz = __ldg(&pos[3 * r + 2]) - __ldg(&pos[3 * c + 2]);

    float sc[HEADS];
#pragma unroll
    for (int h = 0; h < HEADS; h++) {
        float qx = rx * g_M[h][0][0] + ry * g_M[h][1][0] + rz * g_M[h][2][0];
        float qy = rx * g_M[h][0][1] + ry * g_M[h][1][1] + rz * g_M[h][2][1];
        float qz = rx * g_M[h][0][2] + ry * g_M[h][1][2] + rz * g_M[h][2][2];
        sc[h] = rx * qx + ry * qy + rz * qz
              + rx * g_L[h][0] + ry * g_L[h][1] + rz * g_L[h][2] + g_C[h];
    }
    float mx = fmaxf(fmaxf(sc[0], sc[1]), fmaxf(sc[2], sc[3]));
    float ex[HEADS];
    float sum = 0.f;
#pragma unroll
    for (int h = 0; h < HEADS; h++) { ex[h] = __expf(sc[h] - mx); sum += ex[h]; }
    float inv = 1.f / sum;

#pragma unroll
    for (int h = 0; h < HEADS; h++) {
        float a = ex[h] * inv;
        float4* p = &g_acc[h][c];
        asm volatile("red.global.add.v4.f32 [%0], {%1, %2, %3, %4};"
                     :: "l"(p), "f"(a * rx), "f"(a * ry), "f"(a * rz), "f"(a)
                     : "memory");
    }
}

// ---------------------------------------------------------------------------
// node kernel: 1 warp/node; 16-float contraction, warp LayerNorm, SiLU.
// ---------------------------------------------------------------------------
__global__ void node_kernel(const float* __restrict__ bout, const float* __restrict__ gamma,
                            const float* __restrict__ beta, float* __restrict__ out) {
    int gtid = blockIdx.x * blockDim.x + threadIdx.x;
    int n = gtid >> 5;
    int lane = gtid & 31;
    if (n >= N_NODES) return;

    float4 t0 = g_acc[0][n];
    float4 t1 = g_acc[1][n];
    float4 t2 = g_acc[2][n];
    float4 t3 = g_acc[3][n];
    // count = sum_h S_h (softmax over heads sums to 1 per edge)
    float cnt = t0.w + t1.w + t2.w + t3.w;
    float invc = 1.f / fmaxf(cnt, 1.f);

    float acc =
          t0.x * g_A[0][0][lane] + t0.y * g_A[0][1][lane] + t0.z * g_A[0][2][lane] + t0.w * g_U[0][lane]
        + t1.x * g_A[1][0][lane] + t1.y * g_A[1][1][lane] + t1.z * g_A[1][2][lane] + t1.w * g_U[1][lane]
        + t2.x * g_A[2][0][lane] + t2.y * g_A[2][1][lane] + t2.z * g_A[2][2][lane] + t2.w * g_U[2][lane]
        + t3.x * g_A[3][0][lane] + t3.y * g_A[3][1][lane] + t3.z * g_A[3][2][lane] + t3.w * g_U[3][lane];

    float val = acc * invc + bout[lane];

    float s = val, ss = val * val;
#pragma unroll
    for (int o = 16; o > 0; o >>= 1) {
        s  += __shfl_xor_sync(0xffffffffu, s, o);
        ss += __shfl_xor_sync(0xffffffffu, ss, o);
    }
    float mu  = s * (1.f / 32.f);
    float var = ss * (1.f / 32.f) - mu * mu;
    float y = (val - mu) * rsqrtf(var + 1e-5f) * gamma[lane] + beta[lane];
    out[n * 32 + lane] = y * (1.f / (1.f + __expf(-y)));
}

extern "C" void kernel_launch(void* const* d_in, const int* in_sizes, int n_in,
                              void* d_out, int out_size) {
    const float* pos   = (const float*)d_in[0];
    const void*  ei    = d_in[1];
    const float* Wq    = (const float*)d_in[2];
    const float* bq    = (const float*)d_in[3];
    const float* Wk    = (const float*)d_in[4];
    const float* bk    = (const float*)d_in[5];
    const float* Wv    = (const float*)d_in[6];
    const float* bv    = (const float*)d_in[7];
    const float* Wout  = (const float*)d_in[8];
    const float* bout  = (const float*)d_in[9];
    const float* gamma = (const float*)d_in[10];
    const float* beta  = (const float*)d_in[11];
    float* out = (float*)d_out;

    int E = in_sizes[1] / 2;

    init_kernel<<<NZB + 1, 256>>>(ei, Wq, bq, Wk, bk, Wv, bv, Wout, E);
    edge_kernel<<<(E + 255) / 256, 256>>>(pos, ei, E);
    node_kernel<<<(N_NODES * 32 + 255) / 256, 256>>>(bout, gamma, beta, out);
}